// round 2
// baseline (speedup 1.0000x reference)
#include <cuda_runtime.h>

// ReacPartialGbModel: B=4096 independent RK4 integrations, T=256 steps.
// One warp per batch element; lane = hidden unit (H=32).
// All MLP weights register-resident as per-lane column slices.
// h-vector broadcasts via shared memory (STS + 8x uniform LDS.128).

namespace {

constexpr int kT = 256;
constexpr int kB = 4096;
constexpr int kWarpsPerBlock = 4;

__device__ __forceinline__ float tanh_fast(float x) {
    // tanh(x) = sign(x) * (1 - e) / (1 + e),  e = exp(-2|x|)
    // absolute error ~1e-7 everywhere; 2 MUFU + few ALU ops.
    float ax = fabsf(x);
    float e  = __expf(-2.0f * ax);
    float r  = __fdividef(1.0f - e, 1.0f + e);
    return copysignf(r, x);
}

__device__ __forceinline__ float wsum(float v) {
#pragma unroll
    for (int m = 16; m > 0; m >>= 1) v += __shfl_xor_sync(0xffffffffu, v, m);
    return v;
}

__global__ void __launch_bounds__(kWarpsPerBlock * 32)
rk4_kernel(const float* __restrict__ useq, const float* __restrict__ xz0,
           const float* __restrict__ r1W0, const float* __restrict__ r1b0,
           const float* __restrict__ r1W1, const float* __restrict__ r1b1,
           const float* __restrict__ r1W2, const float* __restrict__ r1b2,
           const float* __restrict__ r2W0, const float* __restrict__ r2b0,
           const float* __restrict__ r2W1, const float* __restrict__ r2b1,
           const float* __restrict__ r2W2, const float* __restrict__ r2b2,
           const float* __restrict__ r3W0, const float* __restrict__ r3b0,
           const float* __restrict__ r3W1, const float* __restrict__ r3b1,
           const float* __restrict__ r3W2, const float* __restrict__ r3b2,
           float* __restrict__ out)
{
    const int wslot = threadIdx.x >> 5;
    const int wid   = blockIdx.x * kWarpsPerBlock + wslot;   // batch element
    const int lane  = threadIdx.x & 31;

    __shared__ __align__(16) float sbuf[kWarpsPerBlock][96];
    float* buf = sbuf[wslot];

    // ---- register-resident weights (lane = hidden index) ----
    const float w10 = r1W0[lane], b10 = r1b0[lane];
    const float w20 = r2W0[lane], b20 = r2b0[lane];
    float w11[32], w21[32], w31[32], w30[24];
#pragma unroll
    for (int j = 0; j < 32; ++j) {
        w11[j] = r1W1[j * 32 + lane];
        w21[j] = r2W1[j * 32 + lane];
        w31[j] = r3W1[j * 32 + lane];
    }
#pragma unroll
    for (int k = 0; k < 24; ++k) w30[k] = r3W0[k * 32 + lane];
    const float b30 = r3b0[lane];
    const float b11 = r1b1[lane], b21 = r2b1[lane], b31 = r3b1[lane];
    const float w12 = r1W2[lane], w22 = r2W2[lane], w32 = r3W2[lane];
    const float b12 = r1b2[0],    b22 = r2b2[0],    b32 = r3b2[0];

    // ---- state (replicated across lanes) ----
    const float* xz = xz0 + wid * 26;
    float x0 = xz[0], x1 = xz[1];
    float xp[16], up[8];
#pragma unroll
    for (int k = 0; k < 16; ++k) xp[k] = xz[2 + k];
#pragma unroll
    for (int k = 0; k < 8;  ++k) up[k] = xz[18 + k];

    const float* uptr = useq + wid * kT;
    float2* outp = reinterpret_cast<float2*>(out) + wid * kT;

    // evaluate p1(xa0), p2(xa1), and (if n3) p3 with given layer-0 preact a3
    auto stage = [&](float xa0, float xa1, float a3, int n3,
                     float& r1o, float& r2o, float& r3o) {
        float ha = tanh_fast(fmaf(xa0, w10, b10));
        float hb = tanh_fast(fmaf(xa1, w20, b20));
        float hc = n3 ? tanh_fast(a3) : 0.0f;
        __syncwarp();                       // protect prior reads of buf
        buf[lane]      = ha;
        buf[32 + lane] = hb;
        if (n3) buf[64 + lane] = hc;
        __syncwarp();
        float A0 = 0.f, A1 = 0.f, B0 = 0.f, B1 = 0.f, C0 = 0.f, C1 = 0.f;
        const float4* bv = reinterpret_cast<const float4*>(buf);
#pragma unroll
        for (int q = 0; q < 8; ++q) {
            float4 va = bv[q];
            A0 = fmaf(va.x, w11[4*q+0], A0);
            A1 = fmaf(va.y, w11[4*q+1], A1);
            A0 = fmaf(va.z, w11[4*q+2], A0);
            A1 = fmaf(va.w, w11[4*q+3], A1);
            float4 vb = bv[8 + q];
            B0 = fmaf(vb.x, w21[4*q+0], B0);
            B1 = fmaf(vb.y, w21[4*q+1], B1);
            B0 = fmaf(vb.z, w21[4*q+2], B0);
            B1 = fmaf(vb.w, w21[4*q+3], B1);
            if (n3) {
                float4 vc = bv[16 + q];
                C0 = fmaf(vc.x, w31[4*q+0], C0);
                C1 = fmaf(vc.y, w31[4*q+1], C1);
                C0 = fmaf(vc.z, w31[4*q+2], C0);
                C1 = fmaf(vc.w, w31[4*q+3], C1);
            }
        }
        float h2a = tanh_fast(A0 + A1 + b11);
        float h2b = tanh_fast(B0 + B1 + b21);
        float sa = wsum(h2a * w12);
        float sb = wsum(h2b * w22);
        r1o = (sa + b12) * 0.3f;
        r2o = (sb + b22) * 0.2f;
        if (n3) {
            float h2c = tanh_fast(C0 + C1 + b31);
            float sc = wsum(h2c * w32);
            r3o = (sc + b32) * 0.2f;
        }
    };

    auto kof = [&](float xa0, float xa1, float r1v, float r2v, float r3v,
                   float Caf, float& k0, float& k1v) {
        float Ca  = fmaf(xa0, 0.3f, 0.5f);
        float Cb  = fmaf(xa1, 0.2f, 0.5f);
        float dCa = 0.1f * (Caf - Ca) - r1v;
        float dCb = -0.1f * Cb + r1v - 3.0f * r2v + r3v;
        k0  = dCa * (1.0f / 0.3f);
        k1v = dCb * (1.0f / 0.2f);
    };

#pragma unroll 1
    for (int t = 0; t < kT; ++t) {
        float u = __ldg(uptr + t);
        if (lane == 0) outp[t] = make_float2(x0, x1);   // ys[:,t] = x (pre-update)
        float Caf = fmaf(u, 0.5f, 1.0f);

        float r1s, r2s, r3sA, r3sB, r3sD, dmy;

        // ---- k1 : z = [xp, up] ----
        {
            float sA = b30, sB = 0.f, sC = 0.f;
#pragma unroll
            for (int k = 0; k < 15; k += 3) {
                sA = fmaf(xp[k],     w30[k],     sA);
                sB = fmaf(xp[k + 1], w30[k + 1], sB);
                sC = fmaf(xp[k + 2], w30[k + 2], sC);
            }
            sA = fmaf(xp[15], w30[15], sA);
#pragma unroll
            for (int k = 0; k < 8; k += 2) {
                sB = fmaf(up[k],     w30[16 + k],     sB);
                sC = fmaf(up[k + 1], w30[16 + k + 1], sC);
            }
            float a3 = sA + sB + sC;
            stage(x0, x1, a3, 1, r1s, r2s, r3sA);
        }
        float k10, k11; kof(x0, x1, r1s, r2s, r3sA, Caf, k10, k11);

        // ---- k2 : x + k1/2, z23 = [interp([xp,x]), up] ----
        float xb0 = fmaf(0.5f, k10, x0), xb1 = fmaf(0.5f, k11, x1);
        {
            float sA = b30, sB = 0.f, sC = 0.f;
#pragma unroll
            for (int k = 0; k < 12; k += 3) {
                sA = fmaf(0.5f * (xp[k]     + xp[k + 2]), w30[k],     sA);
                sB = fmaf(0.5f * (xp[k + 1] + xp[k + 3]), w30[k + 1], sB);
                sC = fmaf(0.5f * (xp[k + 2] + xp[k + 4]), w30[k + 2], sC);
            }
            sA = fmaf(0.5f * (xp[12] + xp[14]), w30[12], sA);
            sB = fmaf(0.5f * (xp[13] + xp[15]), w30[13], sB);
            sC = fmaf(0.5f * (xp[14] + x0),     w30[14], sC);
            sA = fmaf(0.5f * (xp[15] + x1),     w30[15], sA);
#pragma unroll
            for (int k = 0; k < 8; k += 2) {
                sB = fmaf(up[k],     w30[16 + k],     sB);
                sC = fmaf(up[k + 1], w30[16 + k + 1], sC);
            }
            float a3 = sA + sB + sC;
            stage(xb0, xb1, a3, 1, r1s, r2s, r3sB);
        }
        float k20, k21; kof(xb0, xb1, r1s, r2s, r3sB, Caf, k20, k21);

        // ---- k3 : x + k2/2, same z23 -> reuse r3sB ----
        float xc0 = fmaf(0.5f, k20, x0), xc1 = fmaf(0.5f, k21, x1);
        stage(xc0, xc1, 0.0f, 0, r1s, r2s, dmy);
        float k30, k31; kof(xc0, xc1, r1s, r2s, r3sB, Caf, k30, k31);

        // ---- k4 : x + k3, z4 = [xp[2:], x, up] ----
        float xd0 = x0 + k30, xd1 = x1 + k31;
        {
            float sA = b30, sB = 0.f, sC = 0.f;
#pragma unroll
            for (int k = 0; k < 12; k += 3) {
                sA = fmaf(xp[k + 2], w30[k],     sA);
                sB = fmaf(xp[k + 3], w30[k + 1], sB);
                sC = fmaf(xp[k + 4], w30[k + 2], sC);
            }
            sA = fmaf(xp[14], w30[12], sA);
            sB = fmaf(xp[15], w30[13], sB);
            sC = fmaf(x0,     w30[14], sC);
            sA = fmaf(x1,     w30[15], sA);
#pragma unroll
            for (int k = 0; k < 8; k += 2) {
                sB = fmaf(up[k],     w30[16 + k],     sB);
                sC = fmaf(up[k + 1], w30[16 + k + 1], sC);
            }
            float a3 = sA + sB + sC;
            stage(xd0, xd1, a3, 1, r1s, r2s, r3sD);
        }
        float k40, k41; kof(xd0, xd1, r1s, r2s, r3sD, Caf, k40, k41);

        // ---- RK4 combine + state shift ----
        float nx0 = x0 + (k10 + 2.0f * (k20 + k30) + k40) * (1.0f / 6.0f);
        float nx1 = x1 + (k11 + 2.0f * (k21 + k31) + k41) * (1.0f / 6.0f);

        float ox0 = x0, ox1 = x1;
#pragma unroll
        for (int k = 0; k < 14; ++k) xp[k] = xp[k + 2];
        xp[14] = ox0; xp[15] = ox1;
#pragma unroll
        for (int k = 0; k < 7; ++k) up[k] = up[k + 1];
        up[7] = u;
        x0 = nx0; x1 = nx1;
    }
}

}  // namespace

extern "C" void kernel_launch(void* const* d_in, const int* in_sizes, int n_in,
                              void* d_out, int out_size) {
    (void)in_sizes; (void)n_in; (void)out_size;
    const float* useq = (const float*)d_in[0];
    const float* xz0  = (const float*)d_in[1];
    const float* r1W0 = (const float*)d_in[2];
    const float* r1b0 = (const float*)d_in[3];
    const float* r1W1 = (const float*)d_in[4];
    const float* r1b1 = (const float*)d_in[5];
    const float* r1W2 = (const float*)d_in[6];
    const float* r1b2 = (const float*)d_in[7];
    const float* r2W0 = (const float*)d_in[8];
    const float* r2b0 = (const float*)d_in[9];
    const float* r2W1 = (const float*)d_in[10];
    const float* r2b1 = (const float*)d_in[11];
    const float* r2W2 = (const float*)d_in[12];
    const float* r2b2 = (const float*)d_in[13];
    const float* r3W0 = (const float*)d_in[14];
    const float* r3b0 = (const float*)d_in[15];
    const float* r3W1 = (const float*)d_in[16];
    const float* r3b1 = (const float*)d_in[17];
    const float* r3W2 = (const float*)d_in[18];
    const float* r3b2 = (const float*)d_in[19];
    float* out = (float*)d_out;

    dim3 block(kWarpsPerBlock * 32);
    dim3 grid(kB / kWarpsPerBlock);
    rk4_kernel<<<grid, block>>>(useq, xz0,
                                r1W0, r1b0, r1W1, r1b1, r1W2, r1b2,
                                r2W0, r2b0, r2W1, r2b1, r2W2, r2b2,
                                r3W0, r3b0, r3W1, r3b1, r3W2, r3b2,
                                out);
}

// round 3
// speedup vs baseline: 2.3966x; 2.3966x over previous
#include <cuda_runtime.h>
#include <math.h>

// ReacPartialGbModel: B=4096 RK4 integrations, T=256 steps.
// r1(x0), r2(x1) are scalar->scalar fixed-weight MLPs -> tabulated per launch
// into cubic Hermite coefficient LUTs (two tiny build kernels).
// r3 (24->32->32->1) evaluated 3x/step; all three evals depend only on
// start-of-step state so they run as interleaved ILP chains.
// One warp per batch element; lane = hidden unit (H=32).

namespace {

constexpr int kT = 256;
constexpr int kB = 4096;
constexpr int kN = 8192;                 // LUT intervals
constexpr float kLo   = -64.0f;
constexpr float kH    = 128.0f / kN;     // 1/64
constexpr float kInvH = kN / 128.0f;     // 64

__device__ float2 g_nodes[2][kN + 1];
__device__ __align__(16) float4 g_lut[2][kN];

// ---------------- build kernel 1: exact node values + derivatives ----------
__global__ void build_nodes(const float* __restrict__ W0, const float* __restrict__ B0,
                            const float* __restrict__ W1, const float* __restrict__ B1,
                            const float* __restrict__ W2, const float* __restrict__ B2,
                            const float* __restrict__ V0, const float* __restrict__ C0,
                            const float* __restrict__ V1, const float* __restrict__ C1,
                            const float* __restrict__ V2, const float* __restrict__ C2)
{
    int idx = blockIdx.x * blockDim.x + threadIdx.x;
    if (idx >= 2 * (kN + 1)) return;
    int net  = idx / (kN + 1);
    int node = idx - net * (kN + 1);
    const float* w0 = net ? V0 : W0;  const float* b0 = net ? C0 : B0;
    const float* w1 = net ? V1 : W1;  const float* b1 = net ? C1 : B1;
    const float* w2 = net ? V2 : W2;  const float* b2 = net ? C2 : B2;

    float x = kLo + node * kH;
    float t0[32], s0[32];
#pragma unroll
    for (int i = 0; i < 32; ++i) {
        float a  = fmaf(w0[i], x, b0[i]);
        float th = tanhf(a);
        t0[i] = th;
        s0[i] = (1.0f - th * th) * w0[i];
    }
    float y = b2[0], d = 0.0f;
    for (int j = 0; j < 32; ++j) {
        float a = b1[j], da = 0.0f;
#pragma unroll
        for (int i = 0; i < 32; ++i) {
            float w = w1[i * 32 + j];
            a  = fmaf(t0[i], w, a);
            da = fmaf(s0[i], w, da);
        }
        float th = tanhf(a);
        y = fmaf(w2[j], th, y);
        d = fmaf(w2[j] * (1.0f - th * th), da, d);
    }
    float std = net ? 0.2f : 0.3f;       // Cbstd : Castd, baked into table
    g_nodes[net][node] = make_float2(y * std, d * std);
}

// ---------------- build kernel 2: Hermite -> polynomial coefficients -------
__global__ void build_coeffs()
{
    int idx = blockIdx.x * blockDim.x + threadIdx.x;
    if (idx >= 2 * kN) return;
    int net = idx / kN, i = idx - net * kN;
    float2 n0 = g_nodes[net][i];
    float2 n1 = g_nodes[net][i + 1];
    float hd0 = kH * n0.y, hd1 = kH * n1.y;
    float dy  = n1.x - n0.x;
    g_lut[net][i] = make_float4(n0.x, hd0,
                                3.0f * dy - 2.0f * hd0 - hd1,
                                -2.0f * dy + hd0 + hd1);
}

// ---------------- main kernel ----------------------------------------------
__device__ __forceinline__ float tanh_fast(float x) {
    float ax = fabsf(x);
    float e  = __expf(-2.0f * ax);
    float r  = __fdividef(1.0f - e, 1.0f + e);
    return copysignf(r, x);
}

__device__ __forceinline__ float lut_eval(const float4* __restrict__ lut, float x) {
    float xf = fmaf(x, kInvH, (float)(kN / 2));
    int i = __float2int_rd(xf);
    i = max(0, min(i, kN - 1));
    float t = xf - (float)i;
    float4 c = __ldg(&lut[i]);
    return fmaf(fmaf(fmaf(c.w, t, c.z), t, c.y), t, c.x);
}

__global__ void __launch_bounds__(128, 3)
rk4_kernel(const float* __restrict__ useq, const float* __restrict__ xz0,
           const float* __restrict__ r3W0, const float* __restrict__ r3b0,
           const float* __restrict__ r3W1, const float* __restrict__ r3b1,
           const float* __restrict__ r3W2, const float* __restrict__ r3b2,
           float* __restrict__ out)
{
    const int wslot = threadIdx.x >> 5;
    const int wid   = blockIdx.x * 4 + wslot;      // batch element
    const int lane  = threadIdx.x & 31;

    __shared__ __align__(16) float sbuf[4][192];   // 2 x 96 per warp (step parity)

    // p3 weights, register-resident (lane = hidden index)
    float w30[24], w31[32];
#pragma unroll
    for (int k = 0; k < 24; ++k) w30[k] = r3W0[k * 32 + lane];
#pragma unroll
    for (int j = 0; j < 32; ++j) w31[j] = r3W1[j * 32 + lane];
    const float b30 = r3b0[lane], b31 = r3b1[lane];
    const float w32 = r3W2[lane], b32 = r3b2[0];

    const float4* lut1 = g_lut[0];
    const float4* lut2 = g_lut[1];

    // state (replicated across lanes)
    const float* xz = xz0 + wid * 26;
    float x0 = xz[0], x1 = xz[1];
    float xp[16], up[8];
#pragma unroll
    for (int k = 0; k < 16; ++k) xp[k] = xz[2 + k];
#pragma unroll
    for (int k = 0; k < 8;  ++k) up[k] = xz[18 + k];

    const float* uptr = useq + wid * kT;
    float2* outp = reinterpret_cast<float2*>(out) + wid * kT;

#pragma unroll 1
    for (int t = 0; t < kT; ++t) {
        float u = __ldg(uptr + t);
        if (lane == 0) outp[t] = make_float2(x0, x1);
        float Caf = fmaf(u, 0.5f, 1.0f);

        // ---- p3 layer-0 shared sub-dots -------------------------------
        float S1a = 0.f, S1b = 0.f, S4a = 0.f, S4b = 0.f, Ua = b30, Ub = 0.f;
#pragma unroll
        for (int k = 0; k < 16; k += 2) {
            S1a = fmaf(xp[k],     w30[k],     S1a);
            S1b = fmaf(xp[k + 1], w30[k + 1], S1b);
        }
#pragma unroll
        for (int k = 0; k < 14; k += 2) {
            S4a = fmaf(xp[k + 2], w30[k],     S4a);
            S4b = fmaf(xp[k + 3], w30[k + 1], S4b);
        }
        S4a = fmaf(x0, w30[14], S4a);
        S4b = fmaf(x1, w30[15], S4b);
#pragma unroll
        for (int k = 0; k < 8; k += 2) {
            Ua = fmaf(up[k],     w30[16 + k], Ua);
            Ub = fmaf(up[k + 1], w30[17 + k], Ub);
        }
        float U  = Ua + Ub;
        float S1 = S1a + S1b, S4 = S4a + S4b;
        float a3_1  = S1 + U;
        float a3_4  = S4 + U;
        float a3_23 = fmaf(0.5f, S1 + S4, U);

        // ---- three p3 evals, interleaved ------------------------------
        float h1 = tanh_fast(a3_1);
        float h2 = tanh_fast(a3_23);
        float h3 = tanh_fast(a3_4);
        float* buf = sbuf[wslot] + (t & 1) * 96;   // step-parity double buffer
        buf[lane]      = h1;
        buf[32 + lane] = h2;
        buf[64 + lane] = h3;
        __syncwarp();
        float C10 = 0.f, C11 = 0.f, C20 = 0.f, C21 = 0.f, C30 = 0.f, C31 = 0.f;
        const float4* bv = reinterpret_cast<const float4*>(buf);
#pragma unroll
        for (int q = 0; q < 8; ++q) {
            float4 v1 = bv[q];
            C10 = fmaf(v1.x, w31[4*q+0], C10);
            C11 = fmaf(v1.y, w31[4*q+1], C11);
            C10 = fmaf(v1.z, w31[4*q+2], C10);
            C11 = fmaf(v1.w, w31[4*q+3], C11);
            float4 v2 = bv[8 + q];
            C20 = fmaf(v2.x, w31[4*q+0], C20);
            C21 = fmaf(v2.y, w31[4*q+1], C21);
            C20 = fmaf(v2.z, w31[4*q+2], C20);
            C21 = fmaf(v2.w, w31[4*q+3], C21);
            float4 v3 = bv[16 + q];
            C30 = fmaf(v3.x, w31[4*q+0], C30);
            C31 = fmaf(v3.y, w31[4*q+1], C31);
            C30 = fmaf(v3.z, w31[4*q+2], C30);
            C31 = fmaf(v3.w, w31[4*q+3], C31);
        }
        float p1 = tanh_fast(C10 + C11 + b31) * w32;
        float p2 = tanh_fast(C20 + C21 + b31) * w32;
        float p3 = tanh_fast(C30 + C31 + b31) * w32;
#pragma unroll
        for (int m = 16; m > 0; m >>= 1) {
            p1 += __shfl_xor_sync(0xffffffffu, p1, m);
            p2 += __shfl_xor_sync(0xffffffffu, p2, m);
            p3 += __shfl_xor_sync(0xffffffffu, p3, m);
        }
        float r3_1  = (p1 + b32) * 0.2f;
        float r3_23 = (p2 + b32) * 0.2f;
        float r3_4  = (p3 + b32) * 0.2f;

        // ---- RK4 k-chain (LUT-based r1/r2) -----------------------------
        auto kof = [&](float xa0, float xa1, float r3v, float& k0, float& k1v) {
            float r1 = lut_eval(lut1, xa0);
            float r2 = lut_eval(lut2, xa1);
            float Ca  = fmaf(xa0, 0.3f, 0.5f);
            float Cb  = fmaf(xa1, 0.2f, 0.5f);
            float dCa = 0.1f * (Caf - Ca) - r1;
            float dCb = fmaf(-0.1f, Cb, r1 - 3.0f * r2 + r3v);
            k0  = dCa * (1.0f / 0.3f);
            k1v = dCb * (1.0f / 0.2f);
        };

        float k10, k11; kof(x0, x1, r3_1, k10, k11);
        float xb0 = fmaf(0.5f, k10, x0), xb1 = fmaf(0.5f, k11, x1);
        float k20, k21; kof(xb0, xb1, r3_23, k20, k21);
        float xc0 = fmaf(0.5f, k20, x0), xc1 = fmaf(0.5f, k21, x1);
        float k30, k31; kof(xc0, xc1, r3_23, k30, k31);
        float xd0 = x0 + k30, xd1 = x1 + k31;
        float k40, k41; kof(xd0, xd1, r3_4, k40, k41);

        float nx0 = fmaf(k10 + 2.0f * (k20 + k30) + k40, 1.0f / 6.0f, x0);
        float nx1 = fmaf(k11 + 2.0f * (k21 + k31) + k41, 1.0f / 6.0f, x1);

        // ---- state shift ------------------------------------------------
        float ox0 = x0, ox1 = x1;
#pragma unroll
        for (int k = 0; k < 14; ++k) xp[k] = xp[k + 2];
        xp[14] = ox0; xp[15] = ox1;
#pragma unroll
        for (int k = 0; k < 7; ++k) up[k] = up[k + 1];
        up[7] = u;
        x0 = nx0; x1 = nx1;
    }
}

}  // namespace

extern "C" void kernel_launch(void* const* d_in, const int* in_sizes, int n_in,
                              void* d_out, int out_size) {
    (void)in_sizes; (void)n_in; (void)out_size;
    const float* useq = (const float*)d_in[0];
    const float* xz0  = (const float*)d_in[1];
    const float* r1W0 = (const float*)d_in[2];
    const float* r1b0 = (const float*)d_in[3];
    const float* r1W1 = (const float*)d_in[4];
    const float* r1b1 = (const float*)d_in[5];
    const float* r1W2 = (const float*)d_in[6];
    const float* r1b2 = (const float*)d_in[7];
    const float* r2W0 = (const float*)d_in[8];
    const float* r2b0 = (const float*)d_in[9];
    const float* r2W1 = (const float*)d_in[10];
    const float* r2b1 = (const float*)d_in[11];
    const float* r2W2 = (const float*)d_in[12];
    const float* r2b2 = (const float*)d_in[13];
    const float* r3W0 = (const float*)d_in[14];
    const float* r3b0 = (const float*)d_in[15];
    const float* r3W1 = (const float*)d_in[16];
    const float* r3b1 = (const float*)d_in[17];
    const float* r3W2 = (const float*)d_in[18];
    const float* r3b2 = (const float*)d_in[19];
    float* out = (float*)d_out;

    build_nodes<<<(2 * (kN + 1) + 127) / 128, 128>>>(
        r1W0, r1b0, r1W1, r1b1, r1W2, r1b2,
        r2W0, r2b0, r2W1, r2b1, r2W2, r2b2);
    build_coeffs<<<(2 * kN + 127) / 128, 128>>>();
    rk4_kernel<<<kB / 4, 128>>>(useq, xz0,
                                r3W0, r3b0, r3W1, r3b1, r3W2, r3b2,
                                out);
}